// round 4
// baseline (speedup 1.0000x reference)
#include <cuda_runtime.h>
#include <cstdint>

#define Bb 32
#define Tt 256
#define Ee 256
#define Hh 512
#define Gg 2048
#define Kk 32
#define NEGV -10000.0f
#define NRNN_CTAS 128

typedef unsigned long long ull;

__device__ float g_xw[2][Tt][Bb][Gg];
__device__ float g_hall[2][Tt][Bb][Hh];
__device__ float g_hbuf[2][2][Bb][Hh];
__device__ float g_feats[Tt][Bb][Kk];
__device__ unsigned g_bar_cnt;

__device__ __forceinline__ float sigf(float x) { return 1.0f / (1.0f + __expf(-x)); }
__device__ __forceinline__ float tanhfast(float x) { return 1.0f - 2.0f / (1.0f + __expf(2.0f * x)); }

__device__ __forceinline__ ull pack2(float lo, float hi) {
    ull r; asm("mov.b64 %0, {%1, %2};" : "=l"(r) : "f"(lo), "f"(hi)); return r;
}
__device__ __forceinline__ float2 unpk2(ull v) {
    float2 r; asm("mov.b64 {%0, %1}, %2;" : "=f"(r.x), "=f"(r.y) : "l"(v)); return r;
}
__device__ __forceinline__ void fma2(ull &acc, ull a, ull b) {
    asm("fma.rn.f32x2 %0, %1, %2, %0;" : "+l"(acc) : "l"(a), "l"(b));
}

__device__ __forceinline__ void grid_barrier(unsigned target) {
    __syncthreads();
    if (threadIdx.x == 0) {
        __threadfence();
        atomicAdd(&g_bar_cnt, 1u);
        while (*((volatile unsigned*)&g_bar_cnt) < target) { }
        __threadfence();
    }
    __syncthreads();
}

// ---------------- K0 ----------------
__global__ void k_init(const float* __restrict__ h0) {
    int i = blockIdx.x * 256 + threadIdx.x;
    ((float*)g_hbuf)[i] = h0[i];
    if (i == 0) g_bar_cnt = 0;
}

// ---------------- K1: xw = emb[sent] @ W_ih^T + b (FFMA2) ----------------
__global__ __launch_bounds__(256) void k_xw(const int* __restrict__ sent,
                                            const float* __restrict__ emb,
                                            const float* __restrict__ Wf,
                                            const float* __restrict__ bf,
                                            const float* __restrict__ Wb,
                                            const float* __restrict__ bb) {
    __shared__ float As[16][64];
    __shared__ float Bs[16][64];
    __shared__ int tok[64];
    __shared__ float bias_sh[64];

    const int tid = threadIdx.x;
    const int m0 = blockIdx.x * 64;
    const int g0 = blockIdx.y * 64;
    const int dir = blockIdx.z;
    const float* W = dir ? Wb : Wf;
    const float* bias = dir ? bb : bf;

    if (tid < 64) {
        int m = m0 + tid;
        tok[tid] = sent[(m & 31) * Tt + (m >> 5)];
        bias_sh[tid] = bias[g0 + tid];
    }
    __syncthreads();

    ull acc2[4][2];
#pragma unroll
    for (int i = 0; i < 4; i++) { acc2[i][0] = 0ull; acc2[i][1] = 0ull; }

    const int mr = tid >> 2;
    const int kq = (tid & 3) * 4;
    const int ty = tid >> 4;
    const int tx = tid & 15;

    for (int kc = 0; kc < Ee; kc += 16) {
        float4 av = *(const float4*)&emb[tok[mr] * Ee + kc + kq];
        float4 bv = *(const float4*)&W[(g0 + mr) * Ee + kc + kq];
        As[kq + 0][mr] = av.x; As[kq + 1][mr] = av.y;
        As[kq + 2][mr] = av.z; As[kq + 3][mr] = av.w;
        Bs[kq + 0][mr] = bv.x; Bs[kq + 1][mr] = bv.y;
        Bs[kq + 2][mr] = bv.z; Bs[kq + 3][mr] = bv.w;
        __syncthreads();
#pragma unroll
        for (int kk = 0; kk < 16; kk++) {
            float a_[4], b_[4];
            *(float4*)a_ = *(const float4*)&As[kk][ty * 4];
            *(float4*)b_ = *(const float4*)&Bs[kk][tx * 4];
            ull bp0 = pack2(b_[0], b_[1]);
            ull bp1 = pack2(b_[2], b_[3]);
#pragma unroll
            for (int i = 0; i < 4; i++) {
                ull ad = pack2(a_[i], a_[i]);
                fma2(acc2[i][0], ad, bp0);
                fma2(acc2[i][1], ad, bp1);
            }
        }
        __syncthreads();
    }

#pragma unroll
    for (int i = 0; i < 4; i++) {
        int m = m0 + ty * 4 + i;
        int t = m >> 5, b = m & 31;
        int tt = dir ? (Tt - 1 - t) : t;
        float2 p0 = unpk2(acc2[i][0]);
        float2 p1 = unpk2(acc2[i][1]);
        float4 o;
        o.x = p0.x + bias_sh[tx * 4 + 0];
        o.y = p0.y + bias_sh[tx * 4 + 1];
        o.z = p1.x + bias_sh[tx * 4 + 2];
        o.w = p1.y + bias_sh[tx * 4 + 3];
        *(float4*)&g_xw[dir][tt][b][g0 + tx * 4] = o;
    }
}

// ---------------- K2: persistent LSTM (FFMA2 inner GEMM) ----------------
#define WPAD 516
#define HPAD 33
#define SM_RNN_FLOATS (32 * WPAD + Hh * HPAD + 4 * 32 * 33 + 256)

__global__ __launch_bounds__(256, 1) void k_rnn(const float* __restrict__ Whf,
                                                const float* __restrict__ Whb,
                                                const float* __restrict__ c0) {
    extern __shared__ float sm[];
    float* w_sh = sm;
    float* h_sh = sm + 32 * WPAD;
    float* zp   = h_sh + Hh * HPAD;
    float* c_sh = zp + 4 * 32 * 33;

    const int tid = threadIdx.x;
    const int dir = blockIdx.x >> 6;
    const int jblock = (blockIdx.x & 63) << 3;
    const float* Wh = dir ? Whb : Whf;

    for (int i = tid; i < 32 * 512; i += 256) {
        int r = i >> 9, k = i & 511;
        int grow = ((r >> 3) << 9) + jblock + (r & 7);
        w_sh[r * WPAD + k] = Wh[grow * Hh + k];
    }
    {
        int b = tid >> 3, jj = tid & 7;
        c_sh[jj * 32 + b] = c0[(dir * Bb + b) * Hh + jblock + jj];
    }

    const int ks = tid >> 6;
    const int gt = tid & 63;
    const int rt = (gt >> 3) << 2;
    const int bt = (gt & 7) << 2;
    const int k0 = ks << 7;
    const int gb = tid >> 3;
    const int gj = tid & 7;
    __syncthreads();

    for (int t = 0; t < Tt; t++) {
        const float* hb = &g_hbuf[t & 1][dir][0][0];
        for (int i4 = tid; i4 < 4096; i4 += 256) {
            int b = i4 >> 7, k4 = (i4 & 127) << 2;
            float4 v = *(const float4*)&hb[b * Hh + k4];
            h_sh[(k4 + 0) * HPAD + b] = v.x;
            h_sh[(k4 + 1) * HPAD + b] = v.y;
            h_sh[(k4 + 2) * HPAD + b] = v.z;
            h_sh[(k4 + 3) * HPAD + b] = v.w;
        }
        float xwv[4];
#pragma unroll
        for (int g4 = 0; g4 < 4; g4++)
            xwv[g4] = g_xw[dir][t][gb][(g4 << 9) + jblock + gj];
        __syncthreads();

        ull A2[4][4];
#pragma unroll
        for (int i = 0; i < 4; i++)
#pragma unroll
            for (int j = 0; j < 4; j++) A2[i][j] = 0ull;

        for (int k = k0; k < k0 + 128; k += 4) {
            float w0[4], w1[4], w2[4], w3[4];
            *(float4*)w0 = *(const float4*)&w_sh[(rt + 0) * WPAD + k];
            *(float4*)w1 = *(const float4*)&w_sh[(rt + 1) * WPAD + k];
            *(float4*)w2 = *(const float4*)&w_sh[(rt + 2) * WPAD + k];
            *(float4*)w3 = *(const float4*)&w_sh[(rt + 3) * WPAD + k];
            ull wp[4][2];
            wp[0][0] = pack2(w0[0], w0[1]); wp[0][1] = pack2(w0[2], w0[3]);
            wp[1][0] = pack2(w1[0], w1[1]); wp[1][1] = pack2(w1[2], w1[3]);
            wp[2][0] = pack2(w2[0], w2[1]); wp[2][1] = pack2(w2[2], w2[3]);
            wp[3][0] = pack2(w3[0], w3[1]); wp[3][1] = pack2(w3[2], w3[3]);
#pragma unroll
            for (int j = 0; j < 4; j++) {
                ull hp0 = pack2(h_sh[(k + 0) * HPAD + bt + j], h_sh[(k + 1) * HPAD + bt + j]);
                ull hp1 = pack2(h_sh[(k + 2) * HPAD + bt + j], h_sh[(k + 3) * HPAD + bt + j]);
#pragma unroll
                for (int i = 0; i < 4; i++) {
                    fma2(A2[i][j], wp[i][0], hp0);
                    fma2(A2[i][j], wp[i][1], hp1);
                }
            }
        }
#pragma unroll
        for (int i = 0; i < 4; i++)
#pragma unroll
            for (int j = 0; j < 4; j++) {
                float2 p = unpk2(A2[i][j]);
                zp[(ks * 32 + rt + i) * 33 + bt + j] = p.x + p.y;
            }
        __syncthreads();

        {
            float z[4];
#pragma unroll
            for (int g4 = 0; g4 < 4; g4++) {
                int r = g4 * 8 + gj;
                z[g4] = xwv[g4]
                      + zp[(0 * 32 + r) * 33 + gb] + zp[(1 * 32 + r) * 33 + gb]
                      + zp[(2 * 32 + r) * 33 + gb] + zp[(3 * 32 + r) * 33 + gb];
            }
            float ig = sigf(z[0]);
            float fg = sigf(z[1]);
            float gg = tanhfast(z[2]);
            float og = sigf(z[3]);
            float c = fg * c_sh[gj * 32 + gb] + ig * gg;
            float h = og * tanhfast(c);
            c_sh[gj * 32 + gb] = c;
            int j = jblock + gj;
            g_hbuf[(t + 1) & 1][dir][gb][j] = h;
            int tt = dir ? (Tt - 1 - t) : t;
            g_hall[dir][tt][gb][j] = h;
        }
        grid_barrier((unsigned)(t + 1) * NRNN_CTAS);
    }
}

// ---------------- K3: feats (reworked: 2 timesteps/CTA, 8 accs/thread) ----------------
// grid 128, block 256. ty=tid>>5 row-group, tx=tid&31 output tag.
__global__ __launch_bounds__(256) void k_feats(const float* __restrict__ Wout,
                                               const float* __restrict__ bout) {
    __shared__ float x_sh[64][132];
    __shared__ float w_sh[32][132];
    const int tid = threadIdx.x;
    const int t0 = blockIdx.x * 2;
    const int ty = tid >> 5;
    const int tx = tid & 31;

    float acc[8];
#pragma unroll
    for (int i = 0; i < 8; i++) acc[i] = 0.0f;

    for (int c0 = 0; c0 < 2 * Hh; c0 += 128) {
        const int half = c0 >= Hh;
        const int cb = c0 - half * Hh;
        // x: 64 rows x 128 cols -> 2048 float4, 8 per thread
        for (int i = tid; i < 2048; i += 256) {
            int r = i >> 5, c4 = (i & 31) << 2;
            int t = t0 + (r >> 5), b = r & 31;
            *(float4*)&x_sh[r][c4] = *(const float4*)&g_hall[half][t][b][cb + c4];
        }
        // w: 32 rows x 128 cols -> 1024 float4, 4 per thread
        for (int i = tid; i < 1024; i += 256) {
            int r = i >> 5, c4 = (i & 31) << 2;
            *(float4*)&w_sh[r][c4] = *(const float4*)&Wout[r * (2 * Hh) + c0 + c4];
        }
        __syncthreads();
#pragma unroll 4
        for (int cc = 0; cc < 128; cc += 4) {
            float wv[4];
            *(float4*)wv = *(const float4*)&w_sh[tx][cc];
#pragma unroll
            for (int ii = 0; ii < 8; ii++) {
                float xv[4];
                *(float4*)xv = *(const float4*)&x_sh[ty * 8 + ii][cc];
                acc[ii] += xv[0] * wv[0] + xv[1] * wv[1] + xv[2] * wv[2] + xv[3] * wv[3];
            }
        }
        __syncthreads();
    }
    float bo = bout[tx];
#pragma unroll
    for (int ii = 0; ii < 8; ii++) {
        int r = ty * 8 + ii;
        int t = t0 + (r >> 5), b = r & 31;
        g_feats[t][b][tx] = acc[ii] + bo;
    }
}

// ---------------- K4: Viterbi ----------------
__global__ __launch_bounds__(32) void k_vit(const float* __restrict__ trans,
                                            float* __restrict__ out) {
    __shared__ unsigned char bp_sh[Tt][Kk];
    const int b = blockIdx.x;
    const int lane = threadIdx.x;

    float tr[Kk];
#pragma unroll
    for (int p = 0; p < Kk; p++) tr[p] = trans[lane * Kk + p];
    const float trstop = trans[31 * Kk + lane];

    float v = (lane == 30) ? 0.0f : NEGV;

    for (int t = 0; t < Tt; t++) {
        float best = -3.0e38f;
        int bp = 0;
#pragma unroll
        for (int p = 0; p < Kk; p++) {
            float vv = __shfl_sync(0xffffffffu, v, p);
            float s = vv + tr[p];
            if (s > best) { best = s; bp = p; }
        }
        v = best + g_feats[t][b][lane];
        bp_sh[t][lane] = (unsigned char)bp;
    }

    float bv = v + trstop;
    int bi = lane;
#pragma unroll
    for (int off = 16; off > 0; off >>= 1) {
        float ov = __shfl_down_sync(0xffffffffu, bv, off);
        int oi = __shfl_down_sync(0xffffffffu, bi, off);
        if (ov > bv || (ov == bv && oi < bi)) { bv = ov; bi = oi; }
    }
    __syncwarp();
    if (lane == 0) {
        out[b] = bv;
        int tag = bi;
        for (int t = Tt - 1; t >= 0; t--) {
            out[Bb + b * Tt + t] = (float)tag;
            tag = bp_sh[t][tag];
        }
    }
}

// ---------------- launch ----------------
extern "C" void kernel_launch(void* const* d_in, const int* in_sizes, int n_in,
                              void* d_out, int out_size) {
    (void)in_sizes; (void)n_in; (void)out_size;
    const int*   sent = (const int*)d_in[0];
    const float* emb  = (const float*)d_in[1];
    const float* Wihf = (const float*)d_in[2];
    const float* Whhf = (const float*)d_in[3];
    const float* bf   = (const float*)d_in[4];
    const float* Wihb = (const float*)d_in[5];
    const float* Whhb = (const float*)d_in[6];
    const float* bb   = (const float*)d_in[7];
    const float* Wout = (const float*)d_in[8];
    const float* bout = (const float*)d_in[9];
    const float* trn  = (const float*)d_in[10];
    const float* h0   = (const float*)d_in[11];
    const float* c0   = (const float*)d_in[12];
    float* out = (float*)d_out;

    const int smem_rnn = SM_RNN_FLOATS * 4;
    cudaFuncSetAttribute(k_rnn, cudaFuncAttributeMaxDynamicSharedMemorySize, smem_rnn);

    k_init<<<128, 256>>>(h0);
    dim3 g1(128, 32, 2);
    k_xw<<<g1, 256>>>(sent, emb, Wihf, bf, Wihb, bb);
    k_rnn<<<NRNN_CTAS, 256, smem_rnn>>>(Whhf, Whhb, c0);
    k_feats<<<Tt / 2, 256>>>(Wout, bout);
    k_vit<<<Bb, 32>>>(trn, out);
}

// round 9
// speedup vs baseline: 1.0724x; 1.0724x over previous
#include <cuda_runtime.h>
#include <cstdint>

#define Bb 32
#define Tt 256
#define Ee 256
#define Hh 512
#define Gg 2048
#define Kk 32
#define NEGV -10000.0f

typedef unsigned long long ull;

// ---------------- scratch ----------------
__device__ float g_xw[2][Tt][Bb][Gg];
__device__ float g_hall[2][Tt][Bb][Hh];
__device__ float g_hbuf[2][2][Bb][Hh];
__device__ float g_feats[Tt][Bb][Kk];
__device__ unsigned g_bar2[64];          // [0]: fwd, [32]: bwd (separate 128B lines)

// ---------------- helpers ----------------
__device__ __forceinline__ float sigf(float x) { return 1.0f / (1.0f + __expf(-x)); }
__device__ __forceinline__ float tanhfast(float x) { return 1.0f - 2.0f / (1.0f + __expf(2.0f * x)); }

__device__ __forceinline__ ull pack2(float lo, float hi) {
    ull r; asm("mov.b64 %0, {%1, %2};" : "=l"(r) : "f"(lo), "f"(hi)); return r;
}
__device__ __forceinline__ float2 unpk2(ull v) {
    float2 r; asm("mov.b64 {%0, %1}, %2;" : "=f"(r.x), "=f"(r.y) : "l"(v)); return r;
}
__device__ __forceinline__ void fma2(ull &acc, ull a, ull b) {
    asm("fma.rn.f32x2 %0, %1, %2, %0;" : "+l"(acc) : "l"(a), "l"(b));
}

__device__ __forceinline__ void grid_barrier_dir(int dir, unsigned target) {
    __syncthreads();
    if (threadIdx.x == 0) {
        unsigned* cnt = &g_bar2[dir * 32];
        __threadfence();
        atomicAdd(cnt, 1u);
        while (*((volatile unsigned*)cnt) < target) { }
        __threadfence();
    }
    __syncthreads();
}

// ---------------- K0 ----------------
__global__ void k_init(const float* __restrict__ h0) {
    int i = blockIdx.x * 256 + threadIdx.x;
    ((float*)g_hbuf)[i] = h0[i];
    if (i == 0) { g_bar2[0] = 0; g_bar2[32] = 0; }
}

// ---------------- K1: xw = emb[sent] @ W_ih^T + b (R1 proven form) ----------------
__global__ __launch_bounds__(256) void k_xw(const int* __restrict__ sent,
                                            const float* __restrict__ emb,
                                            const float* __restrict__ Wf,
                                            const float* __restrict__ bf,
                                            const float* __restrict__ Wb,
                                            const float* __restrict__ bb) {
    __shared__ float As[16][64];
    __shared__ float Bs[16][64];
    __shared__ int tok[64];
    __shared__ float bias_sh[64];

    const int tid = threadIdx.x;
    const int m0 = blockIdx.x * 64;
    const int g0 = blockIdx.y * 64;
    const int dir = blockIdx.z;
    const float* W = dir ? Wb : Wf;
    const float* bias = dir ? bb : bf;

    if (tid < 64) {
        int m = m0 + tid;
        tok[tid] = sent[(m & 31) * Tt + (m >> 5)];
        bias_sh[tid] = bias[g0 + tid];
    }
    __syncthreads();

    float acc[4][4];
#pragma unroll
    for (int i = 0; i < 4; i++)
#pragma unroll
        for (int j = 0; j < 4; j++) acc[i][j] = 0.0f;

    const int mr = tid >> 2;
    const int kq = (tid & 3) * 4;
    const int ty = tid >> 4;
    const int tx = tid & 15;

    for (int kc = 0; kc < Ee; kc += 16) {
        float4 av = *(const float4*)&emb[tok[mr] * Ee + kc + kq];
        float4 bv = *(const float4*)&W[(g0 + mr) * Ee + kc + kq];
        As[kq + 0][mr] = av.x; As[kq + 1][mr] = av.y;
        As[kq + 2][mr] = av.z; As[kq + 3][mr] = av.w;
        Bs[kq + 0][mr] = bv.x; Bs[kq + 1][mr] = bv.y;
        Bs[kq + 2][mr] = bv.z; Bs[kq + 3][mr] = bv.w;
        __syncthreads();
#pragma unroll
        for (int kk = 0; kk < 16; kk++) {
            float a_[4], b_[4];
            *(float4*)a_ = *(const float4*)&As[kk][ty * 4];
            *(float4*)b_ = *(const float4*)&Bs[kk][tx * 4];
#pragma unroll
            for (int i = 0; i < 4; i++)
#pragma unroll
                for (int j = 0; j < 4; j++) acc[i][j] += a_[i] * b_[j];
        }
        __syncthreads();
    }

#pragma unroll
    for (int i = 0; i < 4; i++) {
        int m = m0 + ty * 4 + i;
        int t = m >> 5, b = m & 31;
        int tt = dir ? (Tt - 1 - t) : t;
        float4 o;
        o.x = acc[i][0] + bias_sh[tx * 4 + 0];
        o.y = acc[i][1] + bias_sh[tx * 4 + 1];
        o.z = acc[i][2] + bias_sh[tx * 4 + 2];
        o.w = acc[i][3] + bias_sh[tx * 4 + 3];
        *(float4*)&g_xw[dir][tt][b][g0 + tx * 4] = o;
    }
}

// ---------------- K2: persistent LSTM, FMA2 packed over batch pairs ----------------
// h pairs {h[b], h[b+1]} are contiguous in h_sh[k][b] -> single LDS.64, no packing.
// Only w needs a cheap dup (alu pipe, dual-issues under fma pipe).
#define WPAD 516
#define HPAD 34
#define SM_RNN_FLOATS (32 * WPAD + Hh * HPAD + 4 * 32 * 33 + 256)

__global__ __launch_bounds__(256, 1) void k_rnn(const float* __restrict__ Whf,
                                                const float* __restrict__ Whb,
                                                const float* __restrict__ c0) {
    extern __shared__ float sm[];
    float* w_sh = sm;                     // [32][516]
    float* h_sh = sm + 32 * WPAD;         // [512][34] k-major, b consecutive
    float* zp   = h_sh + Hh * HPAD;       // [4][32][33]
    float* c_sh = zp + 4 * 32 * 33;       // [8][32]

    const int tid = threadIdx.x;
    const int dir = blockIdx.x >> 6;
    const int jblock = (blockIdx.x & 63) << 3;
    const float* Wh = dir ? Whb : Whf;

    for (int i = tid; i < 32 * 512; i += 256) {
        int r = i >> 9, k = i & 511;
        int grow = ((r >> 3) << 9) + jblock + (r & 7);
        w_sh[r * WPAD + k] = Wh[grow * Hh + k];
    }
    {
        int b = tid >> 3, jj = tid & 7;
        c_sh[jj * 32 + b] = c0[(dir * Bb + b) * Hh + jblock + jj];
    }

    const int ks = tid >> 6;          // k-split 0..3
    const int gt = tid & 63;
    const int rt = (gt >> 3) << 2;    // row base
    const int bt = (gt & 7) << 2;     // batch base (multiple of 4 -> 8B aligned pairs)
    const int k0 = ks << 7;
    const int gb = tid >> 3;
    const int gj = tid & 7;
    __syncthreads();

    for (int t = 0; t < Tt; t++) {
        const float* hb = &g_hbuf[t & 1][dir][0][0];
        for (int i4 = tid; i4 < 4096; i4 += 256) {
            int b = i4 >> 7, k4 = (i4 & 127) << 2;
            float4 v = *(const float4*)&hb[b * Hh + k4];
            h_sh[(k4 + 0) * HPAD + b] = v.x;
            h_sh[(k4 + 1) * HPAD + b] = v.y;
            h_sh[(k4 + 2) * HPAD + b] = v.z;
            h_sh[(k4 + 3) * HPAD + b] = v.w;
        }
        float xwv[4];
#pragma unroll
        for (int g4 = 0; g4 < 4; g4++)
            xwv[g4] = g_xw[dir][t][gb][(g4 << 9) + jblock + gj];
        __syncthreads();

        // GEMM: acc packed over batch pairs -> bitwise identical to scalar version
        ull A2[4][2];
#pragma unroll
        for (int i = 0; i < 4; i++) { A2[i][0] = 0ull; A2[i][1] = 0ull; }

        for (int k = k0; k < k0 + 128; k += 4) {
            float w0[4], w1[4], w2[4], w3[4];
            *(float4*)w0 = *(const float4*)&w_sh[(rt + 0) * WPAD + k];
            *(float4*)w1 = *(const float4*)&w_sh[(rt + 1) * WPAD + k];
            *(float4*)w2 = *(const float4*)&w_sh[(rt + 2) * WPAD + k];
            *(float4*)w3 = *(const float4*)&w_sh[(rt + 3) * WPAD + k];
#pragma unroll
            for (int kk = 0; kk < 4; kk++) {
                const float* hrow = &h_sh[(k + kk) * HPAD + bt];
                ull hp0 = *(const ull*)&hrow[0];
                ull hp1 = *(const ull*)&hrow[2];
                ull d0 = pack2(w0[kk], w0[kk]);
                ull d1 = pack2(w1[kk], w1[kk]);
                ull d2 = pack2(w2[kk], w2[kk]);
                ull d3 = pack2(w3[kk], w3[kk]);
                fma2(A2[0][0], d0, hp0); fma2(A2[0][1], d0, hp1);
                fma2(A2[1][0], d1, hp0); fma2(A2[1][1], d1, hp1);
                fma2(A2[2][0], d2, hp0); fma2(A2[2][1], d2, hp1);
                fma2(A2[3][0], d3, hp0); fma2(A2[3][1], d3, hp1);
            }
        }
#pragma unroll
        for (int i = 0; i < 4; i++) {
            float2 p0 = unpk2(A2[i][0]);
            float2 p1 = unpk2(A2[i][1]);
            float* zr = &zp[(ks * 32 + rt + i) * 33 + bt];
            zr[0] = p0.x; zr[1] = p0.y; zr[2] = p1.x; zr[3] = p1.y;
        }
        __syncthreads();

        {
            float z[4];
#pragma unroll
            for (int g4 = 0; g4 < 4; g4++) {
                int r = g4 * 8 + gj;
                z[g4] = xwv[g4]
                      + zp[(0 * 32 + r) * 33 + gb] + zp[(1 * 32 + r) * 33 + gb]
                      + zp[(2 * 32 + r) * 33 + gb] + zp[(3 * 32 + r) * 33 + gb];
            }
            float ig = sigf(z[0]);
            float fg = sigf(z[1]);
            float gg = tanhfast(z[2]);
            float og = sigf(z[3]);
            float c = fg * c_sh[gj * 32 + gb] + ig * gg;
            float h = og * tanhfast(c);
            c_sh[gj * 32 + gb] = c;
            int j = jblock + gj;
            g_hbuf[(t + 1) & 1][dir][gb][j] = h;
            int tt = dir ? (Tt - 1 - t) : t;
            g_hall[dir][tt][gb][j] = h;
        }
        grid_barrier_dir(dir, (unsigned)(t + 1) * 64);
    }
}

// ---------------- K3: feats (R4 proven form) ----------------
__global__ __launch_bounds__(256) void k_feats(const float* __restrict__ Wout,
                                               const float* __restrict__ bout) {
    __shared__ float x_sh[64][132];
    __shared__ float w_sh[32][132];
    const int tid = threadIdx.x;
    const int t0 = blockIdx.x * 2;
    const int ty = tid >> 5;
    const int tx = tid & 31;

    float acc[8];
#pragma unroll
    for (int i = 0; i < 8; i++) acc[i] = 0.0f;

    for (int c0 = 0; c0 < 2 * Hh; c0 += 128) {
        const int half = c0 >= Hh;
        const int cb = c0 - half * Hh;
        for (int i = tid; i < 2048; i += 256) {
            int r = i >> 5, c4 = (i & 31) << 2;
            int t = t0 + (r >> 5), b = r & 31;
            *(float4*)&x_sh[r][c4] = *(const float4*)&g_hall[half][t][b][cb + c4];
        }
        for (int i = tid; i < 1024; i += 256) {
            int r = i >> 5, c4 = (i & 31) << 2;
            *(float4*)&w_sh[r][c4] = *(const float4*)&Wout[r * (2 * Hh) + c0 + c4];
        }
        __syncthreads();
#pragma unroll 4
        for (int cc = 0; cc < 128; cc += 4) {
            float wv[4];
            *(float4*)wv = *(const float4*)&w_sh[tx][cc];
#pragma unroll
            for (int ii = 0; ii < 8; ii++) {
                float xv[4];
                *(float4*)xv = *(const float4*)&x_sh[ty * 8 + ii][cc];
                acc[ii] += xv[0] * wv[0] + xv[1] * wv[1] + xv[2] * wv[2] + xv[3] * wv[3];
            }
        }
        __syncthreads();
    }
    float bo = bout[tx];
#pragma unroll
    for (int ii = 0; ii < 8; ii++) {
        int r = ty * 8 + ii;
        int t = t0 + (r >> 5), b = r & 31;
        g_feats[t][b][tx] = acc[ii] + bo;
    }
}

// ---------------- K4: Viterbi ----------------
__global__ __launch_bounds__(32) void k_vit(const float* __restrict__ trans,
                                            float* __restrict__ out) {
    __shared__ unsigned char bp_sh[Tt][Kk];
    const int b = blockIdx.x;
    const int lane = threadIdx.x;

    float tr[Kk];
#pragma unroll
    for (int p = 0; p < Kk; p++) tr[p] = trans[lane * Kk + p];
    const float trstop = trans[31 * Kk + lane];

    float v = (lane == 30) ? 0.0f : NEGV;

    for (int t = 0; t < Tt; t++) {
        float best = -3.0e38f;
        int bp = 0;
#pragma unroll
        for (int p = 0; p < Kk; p++) {
            float vv = __shfl_sync(0xffffffffu, v, p);
            float s = vv + tr[p];
            if (s > best) { best = s; bp = p; }
        }
        v = best + g_feats[t][b][lane];
        bp_sh[t][lane] = (unsigned char)bp;
    }

    float bv = v + trstop;
    int bi = lane;
#pragma unroll
    for (int off = 16; off > 0; off >>= 1) {
        float ov = __shfl_down_sync(0xffffffffu, bv, off);
        int oi = __shfl_down_sync(0xffffffffu, bi, off);
        if (ov > bv || (ov == bv && oi < bi)) { bv = ov; bi = oi; }
    }
    __syncwarp();
    if (lane == 0) {
        out[b] = bv;
        int tag = bi;
        for (int t = Tt - 1; t >= 0; t--) {
            out[Bb + b * Tt + t] = (float)tag;
            tag = bp_sh[t][tag];
        }
    }
}

// ---------------- launch ----------------
extern "C" void kernel_launch(void* const* d_in, const int* in_sizes, int n_in,
                              void* d_out, int out_size) {
    (void)in_sizes; (void)n_in; (void)out_size;
    const int*   sent = (const int*)d_in[0];
    const float* emb  = (const float*)d_in[1];
    const float* Wihf = (const float*)d_in[2];
    const float* Whhf = (const float*)d_in[3];
    const float* bf   = (const float*)d_in[4];
    const float* Wihb = (const float*)d_in[5];
    const float* Whhb = (const float*)d_in[6];
    const float* bb   = (const float*)d_in[7];
    const float* Wout = (const float*)d_in[8];
    const float* bout = (const float*)d_in[9];
    const float* trn  = (const float*)d_in[10];
    const float* h0   = (const float*)d_in[11];
    const float* c0   = (const float*)d_in[12];
    float* out = (float*)d_out;

    const int smem_rnn = SM_RNN_FLOATS * 4;
    cudaFuncSetAttribute(k_rnn, cudaFuncAttributeMaxDynamicSharedMemorySize, smem_rnn);

    k_init<<<128, 256>>>(h0);
    dim3 g1(128, 32, 2);
    k_xw<<<g1, 256>>>(sent, emb, Wihf, bf, Wihb, bb);
    k_rnn<<<128, 256, smem_rnn>>>(Whhf, Whhb, c0);
    k_feats<<<Tt / 2, 256>>>(Wout, bout);
    k_vit<<<Bb, 32>>>(trn, out);
}

// round 14
// speedup vs baseline: 1.1139x; 1.0387x over previous
#include <cuda_runtime.h>
#include <cstdint>

#define Bb 32
#define Tt 256
#define Ee 256
#define Hh 512
#define Gg 2048
#define Kk 32
#define NEGV -10000.0f

typedef unsigned long long ull;

// ---------------- scratch ----------------
__device__ float g_xw[2][Tt][Bb][Gg];
__device__ float g_hall[2][Tt][Bb][Hh];
__device__ float g_hbuf[2][2][Bb][Hh];
__device__ float g_feats[Tt][Bb][Kk];
__device__ unsigned g_bar2[64];          // [0]: fwd, [32]: bwd

// ---------------- helpers ----------------
__device__ __forceinline__ float sigf(float x) { return 1.0f / (1.0f + __expf(-x)); }
__device__ __forceinline__ float tanhfast(float x) { return 1.0f - 2.0f / (1.0f + __expf(2.0f * x)); }

__device__ __forceinline__ ull pack2(float lo, float hi) {
    ull r; asm("mov.b64 %0, {%1, %2};" : "=l"(r) : "f"(lo), "f"(hi)); return r;
}
__device__ __forceinline__ float2 unpk2(ull v) {
    float2 r; asm("mov.b64 {%0, %1}, %2;" : "=f"(r.x), "=f"(r.y) : "l"(v)); return r;
}
__device__ __forceinline__ void fma2(ull &acc, ull a, ull b) {
    asm("fma.rn.f32x2 %0, %1, %2, %0;" : "+l"(acc) : "l"(a), "l"(b));
}

__device__ __forceinline__ void bar_arrive(unsigned* cnt) {
    asm volatile("red.release.gpu.global.add.u32 [%0], 1;" :: "l"(cnt) : "memory");
}
__device__ __forceinline__ unsigned bar_peek(const unsigned* cnt) {
    unsigned v;
    asm volatile("ld.acquire.gpu.global.u32 %0, [%1];" : "=r"(v) : "l"(cnt) : "memory");
    return v;
}

// ---------------- K0 ----------------
__global__ void k_init(const float* __restrict__ h0) {
    int i = blockIdx.x * 256 + threadIdx.x;
    ((float*)g_hbuf)[i] = h0[i];
    if (i == 0) { g_bar2[0] = 0; g_bar2[32] = 0; }
}

// profiling-slot spacer (no-op)
__global__ void k_dummy() {}

// ---------------- K1: xw = emb[sent] @ W_ih^T + b (FMA2, b-pairs direct) ----------------
__global__ __launch_bounds__(256) void k_xw(const int* __restrict__ sent,
                                            const float* __restrict__ emb,
                                            const float* __restrict__ Wf,
                                            const float* __restrict__ bf,
                                            const float* __restrict__ Wb,
                                            const float* __restrict__ bb) {
    __shared__ float As[16][64];
    __shared__ float Bs[16][64];
    __shared__ int tok[64];
    __shared__ float bias_sh[64];

    const int tid = threadIdx.x;
    const int m0 = blockIdx.x * 64;
    const int g0 = blockIdx.y * 64;
    const int dir = blockIdx.z;
    const float* W = dir ? Wb : Wf;
    const float* bias = dir ? bb : bf;

    if (tid < 64) {
        int m = m0 + tid;
        tok[tid] = sent[(m & 31) * Tt + (m >> 5)];
        bias_sh[tid] = bias[g0 + tid];
    }
    __syncthreads();

    ull acc2[4][2];
#pragma unroll
    for (int i = 0; i < 4; i++) { acc2[i][0] = 0ull; acc2[i][1] = 0ull; }

    const int mr = tid >> 2;
    const int kq = (tid & 3) * 4;
    const int ty = tid >> 4;
    const int tx = tid & 15;

    for (int kc = 0; kc < Ee; kc += 16) {
        float4 av = *(const float4*)&emb[tok[mr] * Ee + kc + kq];
        float4 bv = *(const float4*)&W[(g0 + mr) * Ee + kc + kq];
        As[kq + 0][mr] = av.x; As[kq + 1][mr] = av.y;
        As[kq + 2][mr] = av.z; As[kq + 3][mr] = av.w;
        Bs[kq + 0][mr] = bv.x; Bs[kq + 1][mr] = bv.y;
        Bs[kq + 2][mr] = bv.z; Bs[kq + 3][mr] = bv.w;
        __syncthreads();
#pragma unroll
        for (int kk = 0; kk < 16; kk++) {
            float a_[4];
            *(float4*)a_ = *(const float4*)&As[kk][ty * 4];
            const ull* bp = (const ull*)&Bs[kk][tx * 4];
            ull b0 = bp[0], b1 = bp[1];
#pragma unroll
            for (int i = 0; i < 4; i++) {
                ull ad = pack2(a_[i], a_[i]);
                fma2(acc2[i][0], ad, b0);
                fma2(acc2[i][1], ad, b1);
            }
        }
        __syncthreads();
    }

#pragma unroll
    for (int i = 0; i < 4; i++) {
        int m = m0 + ty * 4 + i;
        int t = m >> 5, b = m & 31;
        int tt = dir ? (Tt - 1 - t) : t;
        float2 p0 = unpk2(acc2[i][0]);
        float2 p1 = unpk2(acc2[i][1]);
        float4 o;
        o.x = p0.x + bias_sh[tx * 4 + 0];
        o.y = p0.y + bias_sh[tx * 4 + 1];
        o.z = p1.x + bias_sh[tx * 4 + 2];
        o.w = p1.y + bias_sh[tx * 4 + 3];
        *(float4*)&g_xw[dir][tt][b][g0 + tx * 4] = o;
    }
}

// ---------------- K2: persistent LSTM, lean critical path ----------------
#define WPAD 516
#define HPAD 34
#define SM_RNN_FLOATS (32 * WPAD + Hh * HPAD + 4 * 32 * 33 + 64)

__global__ __launch_bounds__(256, 1) void k_rnn(const float* __restrict__ Whf,
                                                const float* __restrict__ Whb,
                                                const float* __restrict__ c0) {
    extern __shared__ float sm[];
    float* w_sh = sm;                     // [32][516]
    float* h_sh = sm + 32 * WPAD;         // [512][34] k-major, b consecutive
    float* zp   = h_sh + Hh * HPAD;       // [4][32][33]

    const int tid = threadIdx.x;
    const int dir = blockIdx.x >> 6;
    const int jblock = (blockIdx.x & 63) << 3;
    const float* Wh = dir ? Whb : Whf;
    unsigned* cnt = &g_bar2[dir * 32];

    for (int i = tid; i < 32 * 512; i += 256) {
        int r = i >> 9, k = i & 511;
        int grow = ((r >> 3) << 9) + jblock + (r & 7);
        w_sh[r * WPAD + k] = Wh[grow * Hh + k];
    }

    const int ks = tid >> 6;          // k-split 0..3
    const int gt = tid & 63;
    const int rt = (gt >> 3) << 2;    // row base
    const int bt = (gt & 7) << 2;     // batch base
    const int k0 = ks << 7;
    const int gb = tid >> 3;          // gate batch
    const int gj = tid & 7;           // gate unit (local)

    // c lives in a register (thread (gb,gj) owns cell (gb, jblock+gj) forever)
    float c_reg = c0[(dir * Bb + gb) * Hh + jblock + gj];

    // prefetch xw(0)
    float xwv[4];
#pragma unroll
    for (int g4 = 0; g4 < 4; g4++)
        xwv[g4] = g_xw[dir][0][gb][(g4 << 9) + jblock + gj];

    __syncthreads();

    for (int t = 0; t < Tt; t++) {
        if (tid == 0 && t > 0) {
            unsigned tgt = (unsigned)t * 64;
            while (bar_peek(cnt) < tgt) { }
        }
        __syncthreads();

        // h(t) broadcast: gmem -> smem transposed
        const float* hb = &g_hbuf[t & 1][dir][0][0];
        for (int i4 = tid; i4 < 4096; i4 += 256) {
            int b = i4 >> 7, k4 = (i4 & 127) << 2;
            float4 v = *(const float4*)&hb[b * Hh + k4];
            h_sh[(k4 + 0) * HPAD + b] = v.x;
            h_sh[(k4 + 1) * HPAD + b] = v.y;
            h_sh[(k4 + 2) * HPAD + b] = v.z;
            h_sh[(k4 + 3) * HPAD + b] = v.w;
        }
        __syncthreads();

        // GEMM partial: FMA2 packed over batch pairs (bitwise == scalar)
        ull A2[4][2];
#pragma unroll
        for (int i = 0; i < 4; i++) { A2[i][0] = 0ull; A2[i][1] = 0ull; }

        for (int k = k0; k < k0 + 128; k += 4) {
            float w0[4], w1[4], w2[4], w3[4];
            *(float4*)w0 = *(const float4*)&w_sh[(rt + 0) * WPAD + k];
            *(float4*)w1 = *(const float4*)&w_sh[(rt + 1) * WPAD + k];
            *(float4*)w2 = *(const float4*)&w_sh[(rt + 2) * WPAD + k];
            *(float4*)w3 = *(const float4*)&w_sh[(rt + 3) * WPAD + k];
#pragma unroll
            for (int kk = 0; kk < 4; kk++) {
                const float* hrow = &h_sh[(k + kk) * HPAD + bt];
                ull hp0 = *(const ull*)&hrow[0];
                ull hp1 = *(const ull*)&hrow[2];
                ull d0 = pack2(w0[kk], w0[kk]);
                ull d1 = pack2(w1[kk], w1[kk]);
                ull d2 = pack2(w2[kk], w2[kk]);
                ull d3 = pack2(w3[kk], w3[kk]);
                fma2(A2[0][0], d0, hp0); fma2(A2[0][1], d0, hp1);
                fma2(A2[1][0], d1, hp0); fma2(A2[1][1], d1, hp1);
                fma2(A2[2][0], d2, hp0); fma2(A2[2][1], d2, hp1);
                fma2(A2[3][0], d3, hp0); fma2(A2[3][1], d3, hp1);
            }
        }
#pragma unroll
        for (int i = 0; i < 4; i++) {
            float2 p0 = unpk2(A2[i][0]);
            float2 p1 = unpk2(A2[i][1]);
            float* zr = &zp[(ks * 32 + rt + i) * 33 + bt];
            zr[0] = p0.x; zr[1] = p0.y; zr[2] = p1.x; zr[3] = p1.y;
        }
        __syncthreads();

        // gate stage
        float z[4];
#pragma unroll
        for (int g4 = 0; g4 < 4; g4++) {
            int r = g4 * 8 + gj;
            z[g4] = xwv[g4]
                  + zp[(0 * 32 + r) * 33 + gb] + zp[(1 * 32 + r) * 33 + gb]
                  + zp[(2 * 32 + r) * 33 + gb] + zp[(3 * 32 + r) * 33 + gb];
        }
        float ig = sigf(z[0]);
        float fg = sigf(z[1]);
        float gg = tanhfast(z[2]);
        float og = sigf(z[3]);
        c_reg = fg * c_reg + ig * gg;
        float h = og * tanhfast(c_reg);
        int j = jblock + gj;
        g_hbuf[(t + 1) & 1][dir][gb][j] = h;    // consumed by peers next step
        __syncthreads();                          // all h stores happen-before arrive
        if (tid == 0) bar_arrive(cnt);

        // off critical path: archive h, prefetch next xw
        int tt = dir ? (Tt - 1 - t) : t;
        g_hall[dir][tt][gb][j] = h;
        if (t + 1 < Tt) {
#pragma unroll
            for (int g4 = 0; g4 < 4; g4++)
                xwv[g4] = g_xw[dir][t + 1][gb][(g4 << 9) + jblock + gj];
        }
    }
}

// ---------------- K3: feats ----------------
__global__ __launch_bounds__(256) void k_feats(const float* __restrict__ Wout,
                                               const float* __restrict__ bout) {
    __shared__ float x_sh[64][132];
    __shared__ float w_sh[32][132];
    const int tid = threadIdx.x;
    const int t0 = blockIdx.x * 2;
    const int ty = tid >> 5;
    const int tx = tid & 31;

    float acc[8];
#pragma unroll
    for (int i = 0; i < 8; i++) acc[i] = 0.0f;

    for (int c0 = 0; c0 < 2 * Hh; c0 += 128) {
        const int half = c0 >= Hh;
        const int cb = c0 - half * Hh;
        for (int i = tid; i < 2048; i += 256) {
            int r = i >> 5, c4 = (i & 31) << 2;
            int t = t0 + (r >> 5), b = r & 31;
            *(float4*)&x_sh[r][c4] = *(const float4*)&g_hall[half][t][b][cb + c4];
        }
        for (int i = tid; i < 1024; i += 256) {
            int r = i >> 5, c4 = (i & 31) << 2;
            *(float4*)&w_sh[r][c4] = *(const float4*)&Wout[r * (2 * Hh) + c0 + c4];
        }
        __syncthreads();
#pragma unroll 4
        for (int cc = 0; cc < 128; cc += 4) {
            float wv[4];
            *(float4*)wv = *(const float4*)&w_sh[tx][cc];
#pragma unroll
            for (int ii = 0; ii < 8; ii++) {
                float xv[4];
                *(float4*)xv = *(const float4*)&x_sh[ty * 8 + ii][cc];
                acc[ii] += xv[0] * wv[0] + xv[1] * wv[1] + xv[2] * wv[2] + xv[3] * wv[3];
            }
        }
        __syncthreads();
    }
    float bo = bout[tx];
#pragma unroll
    for (int ii = 0; ii < 8; ii++) {
        int r = ty * 8 + ii;
        int t = t0 + (r >> 5), b = r & 31;
        g_feats[t][b][tx] = acc[ii] + bo;
    }
}

// ---------------- K4: Viterbi ----------------
__global__ __launch_bounds__(32) void k_vit(const float* __restrict__ trans,
                                            float* __restrict__ out) {
    __shared__ unsigned char bp_sh[Tt][Kk];
    const int b = blockIdx.x;
    const int lane = threadIdx.x;

    float tr[Kk];
#pragma unroll
    for (int p = 0; p < Kk; p++) tr[p] = trans[lane * Kk + p];
    const float trstop = trans[31 * Kk + lane];

    float v = (lane == 30) ? 0.0f : NEGV;

    for (int t = 0; t < Tt; t++) {
        float best = -3.0e38f;
        int bp = 0;
#pragma unroll
        for (int p = 0; p < Kk; p++) {
            float vv = __shfl_sync(0xffffffffu, v, p);
            float s = vv + tr[p];
            if (s > best) { best = s; bp = p; }
        }
        v = best + g_feats[t][b][lane];
        bp_sh[t][lane] = (unsigned char)bp;
    }

    float bv = v + trstop;
    int bi = lane;
#pragma unroll
    for (int off = 16; off > 0; off >>= 1) {
        float ov = __shfl_down_sync(0xffffffffu, bv, off);
        int oi = __shfl_down_sync(0xffffffffu, bi, off);
        if (ov > bv || (ov == bv && oi < bi)) { bv = ov; bi = oi; }
    }
    __syncwarp();
    if (lane == 0) {
        out[b] = bv;
        int tag = bi;
        for (int t = Tt - 1; t >= 0; t--) {
            out[Bb + b * Tt + t] = (float)tag;
            tag = bp_sh[t][tag];
        }
    }
}

// ---------------- launch ----------------
extern "C" void kernel_launch(void* const* d_in, const int* in_sizes, int n_in,
                              void* d_out, int out_size) {
    (void)in_sizes; (void)n_in; (void)out_size;
    const int*   sent = (const int*)d_in[0];
    const float* emb  = (const float*)d_in[1];
    const float* Wihf = (const float*)d_in[2];
    const float* Whhf = (const float*)d_in[3];
    const float* bf   = (const float*)d_in[4];
    const float* Wihb = (const float*)d_in[5];
    const float* Whhb = (const float*)d_in[6];
    const float* bb   = (const float*)d_in[7];
    const float* Wout = (const float*)d_in[8];
    const float* bout = (const float*)d_in[9];
    const float* trn  = (const float*)d_in[10];
    const float* h0   = (const float*)d_in[11];
    const float* c0   = (const float*)d_in[12];
    float* out = (float*)d_out;

    const int smem_rnn = SM_RNN_FLOATS * 4;
    cudaFuncSetAttribute(k_rnn, cudaFuncAttributeMaxDynamicSharedMemorySize, smem_rnn);

    k_init<<<128, 256>>>(h0);
    dim3 g1(128, 32, 2);
    k_xw<<<g1, 256>>>(sent, emb, Wihf, bf, Wihb, bb);
    k_dummy<<<1, 1>>>();                 // shifts the fixed ncu slot onto k_rnn
    k_rnn<<<128, 256, smem_rnn>>>(Whhf, Whhb, c0);
    k_feats<<<Tt / 2, 256>>>(Wout, bout);
    k_vit<<<Bb, 32>>>(trn, out);
}